// round 10
// baseline (speedup 1.0000x reference)
#include <cuda_runtime.h>
#include <math.h>

#define BB 128
#define LL 196
#define DD 1024
#define LP1 197

#define GBM 64
#define GBN 64
#define GBK 32
#define SPLITK 4
#define XS 36            // smem row stride: (36*g+t) mod 32 = 4g+t -> conflict-free
#define WSPL 4           // wsum L-split
#define WCH (LL / WSPL)  // 49

// ---------------- scratch (__device__ globals; no allocations allowed) -------
__device__ float g_fr[BB * DD];
__device__ float g_ho[BB * DD];
__device__ float g_fr_e[BB * DD];
__device__ float g_ho_e[BB * DD];
__device__ float g_scores[BB * LP1];
__device__ float g_part[2][SPLITK][BB * DD];   // GEMM split-K partials
__device__ float g_wpart[WSPL][BB * DD];       // wsum split-L partials

__device__ __forceinline__ float fast_tanh(float x) {
    float y;
    asm("tanh.approx.f32 %0, %1;" : "=f"(y) : "f"(x));
    return y;
}

__device__ __forceinline__ float tf32hi(float x) {
    unsigned u;
    asm("cvt.rna.tf32.f32 %0, %1;" : "=r"(u) : "f"(x));
    return __uint_as_float(u);
}

__device__ __forceinline__ void mma8(float d[4],
                                     float a0, float a1, float a2, float a3,
                                     float b0, float b1) {
    asm volatile(
        "mma.sync.aligned.m16n8k8.row.col.f32.tf32.tf32.f32 "
        "{%0,%1,%2,%3},{%4,%5,%6,%7},{%8,%9},{%0,%1,%2,%3};"
        : "+f"(d[0]), "+f"(d[1]), "+f"(d[2]), "+f"(d[3])
        : "r"(__float_as_uint(a0)), "r"(__float_as_uint(a1)),
          "r"(__float_as_uint(a2)), "r"(__float_as_uint(a3)),
          "r"(__float_as_uint(b0)), "r"(__float_as_uint(b1)));
}

// ---------------- tf32 GEMM, split-K, pipelined ------------------------------
// partial[m,n] = sum_{k chunk} X[m,k]*W[n,k].  A = tf32(X), B hi/lo in smem.
// grid: (16 nb, 2 mb x 4 sk, z), 256 threads. fuse_wsum: X = sum of 4 wparts.
__global__ void __launch_bounds__(256, 2) gemm_tf32_kernel(
    const float* __restrict__ X0, const float* __restrict__ W0,
    const float* __restrict__ X1, const float* __restrict__ W1,
    int fuse_wsum)
{
    __shared__ float Xh[GBM * XS];
    __shared__ float Wh[GBN * XS];
    __shared__ float Wl[GBN * XS];

    const int z  = blockIdx.z;
    const float* __restrict__ X = z ? X1 : X0;
    const float* __restrict__ W = z ? W1 : W0;
    const int nb = blockIdx.x;
    const int mb = blockIdx.y & 1;
    const int sk = blockIdx.y >> 1;
    const int kbase = sk * (DD / SPLITK);      // 256-wide K chunk, 8 iters

    const int tid  = threadIdx.x;
    const int lane = tid & 31;
    const int w    = tid >> 5;
    const int g    = lane >> 2;
    const int t    = lane & 3;
    const int wm   = (w & 3) * 16;             // 4 warps x 16 rows
    const int wn   = (w >> 2) * 32;            // 2 warps x 32 cols

    const int lr0 = tid >> 3;                  // loader rows 0..31
    const int lc4 = (tid & 7) * 4;
    const float* Xg = X + (size_t)(mb * GBM) * DD;
    const float* Wg = W + (size_t)(nb * GBN) * DD;
    const size_t wpoff = (size_t)(mb * GBM) * DD;

    float acc[4][4];
#pragma unroll
    for (int j = 0; j < 4; j++)
#pragma unroll
        for (int r = 0; r < 4; r++) acc[j][r] = 0.0f;

    // prologue: load iter 0
    {
        const int k0 = kbase;
#pragma unroll
        for (int j = 0; j < 2; ++j) {
            int row = lr0 + 32 * j;
            size_t off = (size_t)row * DD + k0 + lc4;
            float4 xv;
            if (fuse_wsum) {
                xv = *reinterpret_cast<const float4*>(&g_wpart[0][wpoff + off]);
#pragma unroll
                for (int p = 1; p < WSPL; ++p) {
                    float4 v = *reinterpret_cast<const float4*>(&g_wpart[p][wpoff + off]);
                    xv.x += v.x; xv.y += v.y; xv.z += v.z; xv.w += v.w;
                }
            } else {
                xv = *reinterpret_cast<const float4*>(Xg + off);
            }
            float4 wv = *reinterpret_cast<const float4*>(Wg + off);
            float4 h, wh, wl;
            h.x = tf32hi(xv.x); h.y = tf32hi(xv.y); h.z = tf32hi(xv.z); h.w = tf32hi(xv.w);
            wh.x = tf32hi(wv.x); wh.y = tf32hi(wv.y); wh.z = tf32hi(wv.z); wh.w = tf32hi(wv.w);
            wl.x = tf32hi(wv.x - wh.x); wl.y = tf32hi(wv.y - wh.y);
            wl.z = tf32hi(wv.z - wh.z); wl.w = tf32hi(wv.w - wh.w);
            *reinterpret_cast<float4*>(&Xh[row * XS + lc4]) = h;
            *reinterpret_cast<float4*>(&Wh[row * XS + lc4]) = wh;
            *reinterpret_cast<float4*>(&Wl[row * XS + lc4]) = wl;
        }
    }
    __syncthreads();

    for (int it = 0; it < 8; ++it) {
        float4 xr[2], wr[2];
        if (it < 7) {
            const int k0 = kbase + (it + 1) * GBK;
#pragma unroll
            for (int j = 0; j < 2; ++j) {
                int row = lr0 + 32 * j;
                size_t off = (size_t)row * DD + k0 + lc4;
                if (fuse_wsum) {
                    float4 u = *reinterpret_cast<const float4*>(&g_wpart[0][wpoff + off]);
#pragma unroll
                    for (int p = 1; p < WSPL; ++p) {
                        float4 v = *reinterpret_cast<const float4*>(&g_wpart[p][wpoff + off]);
                        u.x += v.x; u.y += v.y; u.z += v.z; u.w += v.w;
                    }
                    xr[j] = u;
                } else {
                    xr[j] = *reinterpret_cast<const float4*>(Xg + off);
                }
                wr[j] = *reinterpret_cast<const float4*>(Wg + off);
            }
        }

#pragma unroll
        for (int kk = 0; kk < 4; ++kk) {
            const int ko = 8 * kk;
            float a0 = Xh[(wm + g)     * XS + ko + t];
            float a1 = Xh[(wm + g + 8) * XS + ko + t];
            float a2 = Xh[(wm + g)     * XS + ko + t + 4];
            float a3 = Xh[(wm + g + 8) * XS + ko + t + 4];
#pragma unroll
            for (int j = 0; j < 4; ++j) {
                int n = (wn + 8 * j + g) * XS + ko + t;
                float bh0 = Wh[n];
                float bh1 = Wh[n + 4];
                float bl0 = Wl[n];
                float bl1 = Wl[n + 4];
                mma8(acc[j], a0, a1, a2, a3, bl0, bl1);
                mma8(acc[j], a0, a1, a2, a3, bh0, bh1);
            }
        }
        __syncthreads();

        if (it < 7) {
#pragma unroll
            for (int j = 0; j < 2; ++j) {
                int row = lr0 + 32 * j;
                float4 h, wh, wl;
                h.x = tf32hi(xr[j].x); h.y = tf32hi(xr[j].y);
                h.z = tf32hi(xr[j].z); h.w = tf32hi(xr[j].w);
                wh.x = tf32hi(wr[j].x); wh.y = tf32hi(wr[j].y);
                wh.z = tf32hi(wr[j].z); wh.w = tf32hi(wr[j].w);
                wl.x = tf32hi(wr[j].x - wh.x); wl.y = tf32hi(wr[j].y - wh.y);
                wl.z = tf32hi(wr[j].z - wh.z); wl.w = tf32hi(wr[j].w - wh.w);
                *reinterpret_cast<float4*>(&Xh[row * XS + lc4]) = h;
                *reinterpret_cast<float4*>(&Wh[row * XS + lc4]) = wh;
                *reinterpret_cast<float4*>(&Wl[row * XS + lc4]) = wl;
            }
            __syncthreads();
        }
    }

    // store partials: c0,c1 -> [m][2t,2t+1], c2,c3 -> [m+8][...]
    float* pout = &g_part[z][sk][0];
    const int mrow = mb * GBM + wm + g;
#pragma unroll
    for (int j = 0; j < 4; ++j) {
        int n = nb * GBN + wn + 8 * j + 2 * t;
        *reinterpret_cast<float2*>(&pout[(size_t)mrow * DD + n])       = make_float2(acc[j][0], acc[j][1]);
        *reinterpret_cast<float2*>(&pout[(size_t)(mrow + 8) * DD + n]) = make_float2(acc[j][2], acc[j][3]);
    }
}

// ---------------- epilogue: sum split-K partials + bias + act ----------------
// 2 float4 per thread (8 outstanding loads), grid (64, nz), 256 threads.
__global__ void __launch_bounds__(256) epi_kernel(
    float* __restrict__ Y0, const float* __restrict__ b0, int act0,
    float* __restrict__ Y1, const float* __restrict__ b1, int act1)
{
    const int z = blockIdx.y;
    float* Y = z ? Y1 : Y0;
    const float* bias = z ? b1 : b0;
    const int act = z ? act1 : act0;
    const int i4 = (blockIdx.x * 256 + threadIdx.x) * 4;   // [0, 65536)

    float4 s[2];
#pragma unroll
    for (int u = 0; u < 2; ++u)
        s[u] = *reinterpret_cast<const float4*>(&g_part[z][0][i4 + 65536 * u]);
#pragma unroll
    for (int p = 1; p < SPLITK; ++p)
#pragma unroll
        for (int u = 0; u < 2; ++u) {
            float4 v = *reinterpret_cast<const float4*>(&g_part[z][p][i4 + 65536 * u]);
            s[u].x += v.x; s[u].y += v.y; s[u].z += v.z; s[u].w += v.w;
        }
    float4 bv = *reinterpret_cast<const float4*>(&bias[i4 & (DD - 1)]);
#pragma unroll
    for (int u = 0; u < 2; ++u) {
        s[u].x += bv.x; s[u].y += bv.y; s[u].z += bv.z; s[u].w += bv.w;
        if (act == 1) {
            s[u].x = fmaxf(s[u].x, 0.0f); s[u].y = fmaxf(s[u].y, 0.0f);
            s[u].z = fmaxf(s[u].z, 0.0f); s[u].w = fmaxf(s[u].w, 0.0f);
        } else if (act == 2) {
            s[u].x = tanhf(s[u].x); s[u].y = tanhf(s[u].y);
            s[u].z = tanhf(s[u].z); s[u].w = tanhf(s[u].w);
        }
        *reinterpret_cast<float4*>(&Y[i4 + 65536 * u]) = s[u];
    }
}

// ---------------- scores: one warp per l, batched loads ----------------------
__global__ void __launch_bounds__(512) score_kernel(const float* __restrict__ cfe,
                                                    const float* __restrict__ W_a,
                                                    const float* __restrict__ b_a)
{
    __shared__ __align__(16) float s_hoe[DD];
    __shared__ __align__(16) float s_wa[DD];

    const int b   = blockIdx.x;
    const int tid = threadIdx.x;
    for (int i = tid; i < DD; i += 512) {
        s_hoe[i] = g_ho_e[b * DD + i];
        s_wa[i]  = W_a[i];
    }
    __syncthreads();

    const int warp = tid >> 5;
    const int lane = tid & 31;
    const int l = blockIdx.y * 16 + warp;
    if (l >= LP1) return;

    const float* ebase = (l == 0) ? (g_fr_e + (size_t)b * DD)
                                  : (cfe + ((size_t)b * LL + (l - 1)) * (size_t)DD);
    // batch all 8 gmem loads up front (MLP 8), then the tanh/fma chain
    float4 e[8];
#pragma unroll
    for (int i = 0; i < 8; ++i)
        e[i] = *reinterpret_cast<const float4*>(ebase + i * 128 + lane * 4);

    float acc = 0.0f;
#pragma unroll
    for (int i = 0; i < 8; ++i) {
        int d = i * 128 + lane * 4;
        float4 h = *reinterpret_cast<const float4*>(&s_hoe[d]);
        float4 a = *reinterpret_cast<const float4*>(&s_wa[d]);
        acc = fmaf(fast_tanh(e[i].x + h.x), a.x, acc);
        acc = fmaf(fast_tanh(e[i].y + h.y), a.y, acc);
        acc = fmaf(fast_tanh(e[i].z + h.z), a.z, acc);
        acc = fmaf(fast_tanh(e[i].w + h.w), a.w, acc);
    }
#pragma unroll
    for (int off = 16; off > 0; off >>= 1)
        acc += __shfl_down_sync(0xffffffffu, acc, off);
    if (lane == 0) g_scores[b * LP1 + l] = acc + b_a[0];
}

// ---------------- weighted sum, inline softmax, split-L partials -------------
__global__ void __launch_bounds__(128) wsum_part_kernel(const float* __restrict__ conv_feat)
{
    __shared__ float s_pi[WCH];
    __shared__ float s_red[4];
    __shared__ float s_p0;
    const int b   = blockIdx.y;
    const int s   = blockIdx.z;
    const int tid = threadIdx.x;
    const int d   = blockIdx.x * 512 + tid * 4;
    const int l0  = s * WCH;
    const int warp = tid >> 5, lane = tid & 31;

    // --- softmax over 197 scores (recomputed identically per CTA) ---
    const float* sc = g_scores + b * LP1;
    float v0 = sc[tid];                                  // tid < 128 < 197
    float v1 = (tid + 128 < LP1) ? sc[tid + 128] : -1e30f;
    float m = fmaxf(v0, v1);
#pragma unroll
    for (int off = 16; off > 0; off >>= 1)
        m = fmaxf(m, __shfl_xor_sync(0xffffffffu, m, off));
    if (lane == 0) s_red[warp] = m;
    __syncthreads();
    float mx = fmaxf(fmaxf(s_red[0], s_red[1]), fmaxf(s_red[2], s_red[3]));
    float e = expf(v0 - mx) + ((tid + 128 < LP1) ? expf(v1 - mx) : 0.0f);
#pragma unroll
    for (int off = 16; off > 0; off >>= 1)
        e += __shfl_xor_sync(0xffffffffu, e, off);
    __syncthreads();
    if (lane == 0) s_red[warp] = e;
    __syncthreads();
    const float inv = 1.0f / (s_red[0] + s_red[1] + s_red[2] + s_red[3]);

    if (tid < WCH) s_pi[tid] = expf(sc[1 + l0 + tid] - mx) * inv;
    if (tid == 0)  s_p0 = expf(sc[0] - mx) * inv;
    __syncthreads();

    // --- weighted sum over this CTA's L chunk ---
    float4 acc;
    if (s == 0) {
        const float p0 = s_p0;
        float4 fr4 = *reinterpret_cast<const float4*>(&g_fr[b * DD + d]);
        float4 ho4 = *reinterpret_cast<const float4*>(&g_ho[b * DD + d]);
        acc.x = fmaf(p0, fr4.x, ho4.x);
        acc.y = fmaf(p0, fr4.y, ho4.y);
        acc.z = fmaf(p0, fr4.z, ho4.z);
        acc.w = fmaf(p0, fr4.w, ho4.w);
    } else {
        acc = make_float4(0.0f, 0.0f, 0.0f, 0.0f);
    }

    const float* cf = conv_feat + ((size_t)b * LL + l0) * DD + d;
#pragma unroll 7
    for (int l = 0; l < WCH; ++l) {
        float4 v = *reinterpret_cast<const float4*>(cf + (size_t)l * DD);
        float p = s_pi[l];
        acc.x = fmaf(p, v.x, acc.x);
        acc.y = fmaf(p, v.y, acc.y);
        acc.z = fmaf(p, v.z, acc.z);
        acc.w = fmaf(p, v.w, acc.w);
    }
    *reinterpret_cast<float4*>(&g_wpart[s][b * DD + d]) = acc;
}

// ---------------- launch -----------------------------------------------------
extern "C" void kernel_launch(void* const* d_in, const int* in_sizes, int n_in,
                              void* d_out, int out_size)
{
    const float* h_out       = (const float*)d_in[0];
    const float* fake_region = (const float*)d_in[1];
    const float* conv_feat   = (const float*)d_in[2];
    const float* conv_embed  = (const float*)d_in[3];
    const float* W_fr  = (const float*)d_in[4];
    const float* b_fr  = (const float*)d_in[5];
    const float* W_fre = (const float*)d_in[6];
    const float* b_fre = (const float*)d_in[7];
    const float* W_ho  = (const float*)d_in[8];
    const float* b_ho  = (const float*)d_in[9];
    const float* W_hoe = (const float*)d_in[10];
    const float* b_hoe = (const float*)d_in[11];
    const float* W_a   = (const float*)d_in[12];
    const float* b_a   = (const float*)d_in[13];
    const float* W_h   = (const float*)d_in[14];
    const float* b_h   = (const float*)d_in[15];
    float* out = (float*)d_out;

    float *p_fr, *p_ho, *p_fr_e, *p_ho_e;
    cudaGetSymbolAddress((void**)&p_fr,   g_fr);
    cudaGetSymbolAddress((void**)&p_ho,   g_ho);
    cudaGetSymbolAddress((void**)&p_fr_e, g_fr_e);
    cudaGetSymbolAddress((void**)&p_ho_e, g_ho_e);

    const dim3 gg2(DD / GBN, (BB / GBM) * SPLITK, 2);   // 16 x 8 x 2
    const dim3 gg1(DD / GBN, (BB / GBM) * SPLITK, 1);
    const dim3 ge2(64, 2);
    const dim3 ge1(64, 1);

    // stage 1: fr = relu(fake_region@W_fr^T+b), ho = tanh(h_out@W_ho^T+b)
    gemm_tf32_kernel<<<gg2, 256>>>(fake_region, W_fr, h_out, W_ho, 0);
    epi_kernel<<<ge2, 256>>>(p_fr, b_fr, 1, p_ho, b_ho, 2);
    // stage 2: fr_e, ho_e (no activation)
    gemm_tf32_kernel<<<gg2, 256>>>(p_fr, W_fre, p_ho, W_hoe, 0);
    epi_kernel<<<ge2, 256>>>(p_fr_e, b_fre, 0, p_ho_e, b_hoe, 0);
    // attention scores
    score_kernel<<<dim3(BB, 13), 512>>>(conv_embed, W_a, b_a);
    // softmax (inline) + visAtt + ho, split-L partials
    wsum_part_kernel<<<dim3(2, BB, WSPL), 128>>>(conv_feat);
    // stage 3: h = tanh((sum wparts)@W_h^T + b_h), X summed in loader
    gemm_tf32_kernel<<<gg1, 256>>>(nullptr, W_h, nullptr, W_h, 1);
    epi_kernel<<<ge1, 256>>>(out, b_h, 2, out, b_h, 2);
}

// round 11
// speedup vs baseline: 1.0851x; 1.0851x over previous
#include <cuda_runtime.h>
#include <math.h>

#define BB 128
#define LL 196
#define DD 1024
#define LP1 197

#define GBM 64
#define GBN 64
#define GBK 32
#define SPLITK 4
#define XS 36            // smem row stride: (36*g+t) mod 32 = 4g+t -> conflict-free
#define WSPL 2           // wsum L-split
#define WCH (LL / WSPL)  // 98

// ---------------- scratch (__device__ globals; no allocations allowed) -------
__device__ float g_scores[BB * LP1];
__device__ float g_PI[BB * LP1];
__device__ float g_part1[2][SPLITK][BB * DD];  // stage-1 partials; reused by stage-3
__device__ float g_part2[2][SPLITK][BB * DD];  // stage-2 partials
__device__ float g_wpart[WSPL][BB * DD];       // wsum split-L partials

__device__ __forceinline__ float fast_tanh(float x) {
    float y;
    asm("tanh.approx.f32 %0, %1;" : "=f"(y) : "f"(x));
    return y;
}

__device__ __forceinline__ float tf32hi(float x) {
    unsigned u;
    asm("cvt.rna.tf32.f32 %0, %1;" : "=r"(u) : "f"(x));
    return __uint_as_float(u);
}

__device__ __forceinline__ void mma8(float d[4],
                                     float a0, float a1, float a2, float a3,
                                     float b0, float b1) {
    asm volatile(
        "mma.sync.aligned.m16n8k8.row.col.f32.tf32.tf32.f32 "
        "{%0,%1,%2,%3},{%4,%5,%6,%7},{%8,%9},{%0,%1,%2,%3};"
        : "+f"(d[0]), "+f"(d[1]), "+f"(d[2]), "+f"(d[3])
        : "r"(__float_as_uint(a0)), "r"(__float_as_uint(a1)),
          "r"(__float_as_uint(a2)), "r"(__float_as_uint(a3)),
          "r"(__float_as_uint(b0)), "r"(__float_as_uint(b1)));
}

// X-tile element loader (float4 at global row gm, col kc):
// xmode 0: direct from X.  xmode 1: act(sum stage-1 partials + xb)  (z=0 relu, z=1 tanh).
// xmode 2: g_wpart[0]+g_wpart[1].
__device__ __forceinline__ float4 load_x_f4(const float* __restrict__ X,
                                            const float* __restrict__ xb,
                                            int xmode, int z, int gm, int kc)
{
    const size_t off = (size_t)gm * DD + kc;
    if (xmode == 0)
        return *reinterpret_cast<const float4*>(X + off);
    if (xmode == 2) {
        float4 u = *reinterpret_cast<const float4*>(&g_wpart[0][off]);
        float4 v = *reinterpret_cast<const float4*>(&g_wpart[1][off]);
        return make_float4(u.x + v.x, u.y + v.y, u.z + v.z, u.w + v.w);
    }
    // xmode 1: reconstruct stage-1 output
    float4 s = *reinterpret_cast<const float4*>(xb + kc);
#pragma unroll
    for (int p = 0; p < SPLITK; ++p) {
        float4 v = *reinterpret_cast<const float4*>(&g_part1[z][p][off]);
        s.x += v.x; s.y += v.y; s.z += v.z; s.w += v.w;
    }
    if (z == 0) {
        s.x = fmaxf(s.x, 0.0f); s.y = fmaxf(s.y, 0.0f);
        s.z = fmaxf(s.z, 0.0f); s.w = fmaxf(s.w, 0.0f);
    } else {
        s.x = tanhf(s.x); s.y = tanhf(s.y); s.z = tanhf(s.z); s.w = tanhf(s.w);
    }
    return s;
}

// ---------------- tf32 GEMM, split-K, pipelined ------------------------------
// partial[m,n] = sum_{k chunk} X[m,k]*W[n,k].  A = tf32(X), B hi/lo in smem.
// grid: (16 nb, 2 mb x 4 sk, z), 256 threads.
__global__ void __launch_bounds__(256, 2) gemm_tf32_kernel(
    const float* __restrict__ X0, const float* __restrict__ W0,
    const float* __restrict__ X1, const float* __restrict__ W1,
    const float* __restrict__ xb0, const float* __restrict__ xb1,
    int xmode, int pbuf)
{
    __shared__ float Xh[GBM * XS];
    __shared__ float Wh[GBN * XS];
    __shared__ float Wl[GBN * XS];

    const int z  = blockIdx.z;
    const float* __restrict__ X  = z ? X1 : X0;
    const float* __restrict__ W  = z ? W1 : W0;
    const float* __restrict__ xb = z ? xb1 : xb0;
    const int nb = blockIdx.x;
    const int mb = blockIdx.y & 1;
    const int sk = blockIdx.y >> 1;
    const int kbase = sk * (DD / SPLITK);      // 256-wide K chunk, 8 iters

    const int tid  = threadIdx.x;
    const int lane = tid & 31;
    const int w    = tid >> 5;
    const int g    = lane >> 2;
    const int t    = lane & 3;
    const int wm   = (w & 3) * 16;             // 4 warps x 16 rows
    const int wn   = (w >> 2) * 32;            // 2 warps x 32 cols

    const int lr0 = tid >> 3;                  // loader rows 0..31
    const int lc4 = (tid & 7) * 4;
    const float* Wg = W + (size_t)(nb * GBN) * DD;

    float acc[4][4];
#pragma unroll
    for (int j = 0; j < 4; j++)
#pragma unroll
        for (int r = 0; r < 4; r++) acc[j][r] = 0.0f;

    // prologue: load iter 0
    {
        const int k0 = kbase;
#pragma unroll
        for (int j = 0; j < 2; ++j) {
            int row = lr0 + 32 * j;
            float4 xv = load_x_f4(X, xb, xmode, z, mb * GBM + row, k0 + lc4);
            float4 wv = *reinterpret_cast<const float4*>(Wg + (size_t)row * DD + k0 + lc4);
            float4 h, wh, wl;
            h.x = tf32hi(xv.x); h.y = tf32hi(xv.y); h.z = tf32hi(xv.z); h.w = tf32hi(xv.w);
            wh.x = tf32hi(wv.x); wh.y = tf32hi(wv.y); wh.z = tf32hi(wv.z); wh.w = tf32hi(wv.w);
            wl.x = tf32hi(wv.x - wh.x); wl.y = tf32hi(wv.y - wh.y);
            wl.z = tf32hi(wv.z - wh.z); wl.w = tf32hi(wv.w - wh.w);
            *reinterpret_cast<float4*>(&Xh[row * XS + lc4]) = h;
            *reinterpret_cast<float4*>(&Wh[row * XS + lc4]) = wh;
            *reinterpret_cast<float4*>(&Wl[row * XS + lc4]) = wl;
        }
    }
    __syncthreads();

    for (int it = 0; it < 8; ++it) {
        float4 xr[2], wr[2];
        if (it < 7) {
            const int k0 = kbase + (it + 1) * GBK;
#pragma unroll
            for (int j = 0; j < 2; ++j) {
                int row = lr0 + 32 * j;
                xr[j] = load_x_f4(X, xb, xmode, z, mb * GBM + row, k0 + lc4);
                wr[j] = *reinterpret_cast<const float4*>(Wg + (size_t)row * DD + k0 + lc4);
            }
        }

#pragma unroll
        for (int kk = 0; kk < 4; ++kk) {
            const int ko = 8 * kk;
            float a0 = Xh[(wm + g)     * XS + ko + t];
            float a1 = Xh[(wm + g + 8) * XS + ko + t];
            float a2 = Xh[(wm + g)     * XS + ko + t + 4];
            float a3 = Xh[(wm + g + 8) * XS + ko + t + 4];
#pragma unroll
            for (int j = 0; j < 4; ++j) {
                int n = (wn + 8 * j + g) * XS + ko + t;
                float bh0 = Wh[n];
                float bh1 = Wh[n + 4];
                float bl0 = Wl[n];
                float bl1 = Wl[n + 4];
                mma8(acc[j], a0, a1, a2, a3, bl0, bl1);
                mma8(acc[j], a0, a1, a2, a3, bh0, bh1);
            }
        }
        __syncthreads();

        if (it < 7) {
#pragma unroll
            for (int j = 0; j < 2; ++j) {
                int row = lr0 + 32 * j;
                float4 h, wh, wl;
                h.x = tf32hi(xr[j].x); h.y = tf32hi(xr[j].y);
                h.z = tf32hi(xr[j].z); h.w = tf32hi(xr[j].w);
                wh.x = tf32hi(wr[j].x); wh.y = tf32hi(wr[j].y);
                wh.z = tf32hi(wr[j].z); wh.w = tf32hi(wr[j].w);
                wl.x = tf32hi(wr[j].x - wh.x); wl.y = tf32hi(wr[j].y - wh.y);
                wl.z = tf32hi(wr[j].z - wh.z); wl.w = tf32hi(wr[j].w - wh.w);
                *reinterpret_cast<float4*>(&Xh[row * XS + lc4]) = h;
                *reinterpret_cast<float4*>(&Wh[row * XS + lc4]) = wh;
                *reinterpret_cast<float4*>(&Wl[row * XS + lc4]) = wl;
            }
            __syncthreads();
        }
    }

    // store partials: c0,c1 -> [m][2t,2t+1], c2,c3 -> [m+8][...]
    float* pout = pbuf ? &g_part2[z][sk][0] : &g_part1[z][sk][0];
    const int mrow = mb * GBM + wm + g;
#pragma unroll
    for (int j = 0; j < 4; ++j) {
        int n = nb * GBN + wn + 8 * j + 2 * t;
        *reinterpret_cast<float2*>(&pout[(size_t)mrow * DD + n])       = make_float2(acc[j][0], acc[j][1]);
        *reinterpret_cast<float2*>(&pout[(size_t)(mrow + 8) * DD + n]) = make_float2(acc[j][2], acc[j][3]);
    }
}

// ---------------- final epilogue: sum stage-3 partials + bias + tanh ---------
__global__ void __launch_bounds__(256) epi_kernel(float* __restrict__ Y,
                                                  const float* __restrict__ bias)
{
    const int i4 = (blockIdx.x * 256 + threadIdx.x) * 4;
    float4 s = *reinterpret_cast<const float4*>(&bias[i4 & (DD - 1)]);
#pragma unroll
    for (int p = 0; p < SPLITK; ++p) {
        float4 v = *reinterpret_cast<const float4*>(&g_part1[0][p][i4]);
        s.x += v.x; s.y += v.y; s.z += v.z; s.w += v.w;
    }
    s.x = tanhf(s.x); s.y = tanhf(s.y); s.z = tanhf(s.z); s.w = tanhf(s.w);
    *reinterpret_cast<float4*>(&Y[i4]) = s;
}

// ---------------- scores: one warp per l, fused fr_e/ho_e reconstruction -----
__global__ void __launch_bounds__(512) score_kernel(const float* __restrict__ cfe,
                                                    const float* __restrict__ W_a,
                                                    const float* __restrict__ b_a,
                                                    const float* __restrict__ b_fre,
                                                    const float* __restrict__ b_hoe)
{
    __shared__ __align__(16) float s_hoe[DD];
    __shared__ __align__(16) float s_wa[DD];

    const int b   = blockIdx.x;
    const int tid = threadIdx.x;
    for (int i = tid; i < DD; i += 512) {
        float s = b_hoe[i];
#pragma unroll
        for (int p = 0; p < SPLITK; ++p)
            s += g_part2[1][p][(size_t)b * DD + i];
        s_hoe[i] = s;
        s_wa[i]  = W_a[i];
    }
    __syncthreads();

    const int warp = tid >> 5;
    const int lane = tid & 31;
    const int l = blockIdx.y * 16 + warp;
    if (l >= LP1) return;

    const float* ebase = cfe + ((size_t)b * LL + (l - 1)) * (size_t)DD;
    float acc = 0.0f;
#pragma unroll
    for (int i = 0; i < 8; ++i) {
        int d = i * 128 + lane * 4;
        float4 e;
        if (l == 0) {            // fr_e reconstructed from stage-2 partials
            e = *reinterpret_cast<const float4*>(&b_fre[d]);
#pragma unroll
            for (int p = 0; p < SPLITK; ++p) {
                float4 v = *reinterpret_cast<const float4*>(&g_part2[0][p][(size_t)b * DD + d]);
                e.x += v.x; e.y += v.y; e.z += v.z; e.w += v.w;
            }
        } else {
            e = *reinterpret_cast<const float4*>(ebase + d);
        }
        float4 h = *reinterpret_cast<const float4*>(&s_hoe[d]);
        float4 a = *reinterpret_cast<const float4*>(&s_wa[d]);
        acc = fmaf(fast_tanh(e.x + h.x), a.x, acc);
        acc = fmaf(fast_tanh(e.y + h.y), a.y, acc);
        acc = fmaf(fast_tanh(e.z + h.z), a.z, acc);
        acc = fmaf(fast_tanh(e.w + h.w), a.w, acc);
    }
#pragma unroll
    for (int off = 16; off > 0; off >>= 1)
        acc += __shfl_down_sync(0xffffffffu, acc, off);
    if (lane == 0) g_scores[b * LP1 + l] = acc + b_a[0];
}

// ---------------- softmax over 197 scores, one CTA per b ---------------------
__global__ void softmax_kernel()
{
    __shared__ float s_red[8];
    const int b   = blockIdx.x;
    const int tid = threadIdx.x;
    const int warp = tid >> 5, lane = tid & 31;

    float v = (tid < LP1) ? g_scores[b * LP1 + tid] : -1e30f;
    float m = v;
#pragma unroll
    for (int off = 16; off > 0; off >>= 1)
        m = fmaxf(m, __shfl_xor_sync(0xffffffffu, m, off));
    if (lane == 0) s_red[warp] = m;
    __syncthreads();
    if (tid == 0) {
        float mm = s_red[0];
#pragma unroll
        for (int i = 1; i < 8; i++) mm = fmaxf(mm, s_red[i]);
        s_red[0] = mm;
    }
    __syncthreads();
    const float mx = s_red[0];
    float pv = (tid < LP1) ? expf(v - mx) : 0.0f;
    float ssum = pv;
#pragma unroll
    for (int off = 16; off > 0; off >>= 1)
        ssum += __shfl_xor_sync(0xffffffffu, ssum, off);
    __syncthreads();
    if (lane == 0) s_red[warp] = ssum;
    __syncthreads();
    if (tid == 0) {
        float tsum = 0.0f;
#pragma unroll
        for (int i = 0; i < 8; i++) tsum += s_red[i];
        s_red[0] = tsum;
    }
    __syncthreads();
    const float inv = 1.0f / s_red[0];
    if (tid < LP1) g_PI[b * LP1 + tid] = pv * inv;
}

// ---------------- weighted sum, fused fr/ho reconstruction, split-L ----------
__global__ void __launch_bounds__(128) wsum_part_kernel(const float* __restrict__ conv_feat,
                                                        const float* __restrict__ b_fr,
                                                        const float* __restrict__ b_ho)
{
    __shared__ float s_pi[WCH];
    const int b = blockIdx.y;
    const int s = blockIdx.z;
    const int d = blockIdx.x * 512 + threadIdx.x * 4;
    const int l0 = s * WCH;

    for (int i = threadIdx.x; i < WCH; i += 128)
        s_pi[i] = g_PI[b * LP1 + 1 + l0 + i];
    __syncthreads();

    float4 acc;
    if (s == 0) {
        const float p0 = g_PI[b * LP1];
        // fr = relu(sum part1[0] + b_fr), ho = tanh(sum part1[1] + b_ho)
        float4 fr4 = *reinterpret_cast<const float4*>(&b_fr[d]);
        float4 ho4 = *reinterpret_cast<const float4*>(&b_ho[d]);
#pragma unroll
        for (int p = 0; p < SPLITK; ++p) {
            float4 u = *reinterpret_cast<const float4*>(&g_part1[0][p][(size_t)b * DD + d]);
            float4 v = *reinterpret_cast<const float4*>(&g_part1[1][p][(size_t)b * DD + d]);
            fr4.x += u.x; fr4.y += u.y; fr4.z += u.z; fr4.w += u.w;
            ho4.x += v.x; ho4.y += v.y; ho4.z += v.z; ho4.w += v.w;
        }
        fr4.x = fmaxf(fr4.x, 0.0f); fr4.y = fmaxf(fr4.y, 0.0f);
        fr4.z = fmaxf(fr4.z, 0.0f); fr4.w = fmaxf(fr4.w, 0.0f);
        ho4.x = tanhf(ho4.x); ho4.y = tanhf(ho4.y);
        ho4.z = tanhf(ho4.z); ho4.w = tanhf(ho4.w);
        acc.x = fmaf(p0, fr4.x, ho4.x);
        acc.y = fmaf(p0, fr4.y, ho4.y);
        acc.z = fmaf(p0, fr4.z, ho4.z);
        acc.w = fmaf(p0, fr4.w, ho4.w);
    } else {
        acc = make_float4(0.0f, 0.0f, 0.0f, 0.0f);
    }

    const float* cf = conv_feat + ((size_t)b * LL + l0) * DD + d;
#pragma unroll 7
    for (int l = 0; l < WCH; ++l) {
        float4 v = *reinterpret_cast<const float4*>(cf + (size_t)l * DD);
        float p = s_pi[l];
        acc.x = fmaf(p, v.x, acc.x);
        acc.y = fmaf(p, v.y, acc.y);
        acc.z = fmaf(p, v.z, acc.z);
        acc.w = fmaf(p, v.w, acc.w);
    }
    *reinterpret_cast<float4*>(&g_wpart[s][b * DD + d]) = acc;
}

// ---------------- launch -----------------------------------------------------
extern "C" void kernel_launch(void* const* d_in, const int* in_sizes, int n_in,
                              void* d_out, int out_size)
{
    const float* h_out       = (const float*)d_in[0];
    const float* fake_region = (const float*)d_in[1];
    const float* conv_feat   = (const float*)d_in[2];
    const float* conv_embed  = (const float*)d_in[3];
    const float* W_fr  = (const float*)d_in[4];
    const float* b_fr  = (const float*)d_in[5];
    const float* W_fre = (const float*)d_in[6];
    const float* b_fre = (const float*)d_in[7];
    const float* W_ho  = (const float*)d_in[8];
    const float* b_ho  = (const float*)d_in[9];
    const float* W_hoe = (const float*)d_in[10];
    const float* b_hoe = (const float*)d_in[11];
    const float* W_a   = (const float*)d_in[12];
    const float* b_a   = (const float*)d_in[13];
    const float* W_h   = (const float*)d_in[14];
    const float* b_h   = (const float*)d_in[15];
    float* out = (float*)d_out;

    const dim3 gg2(DD / GBN, (BB / GBM) * SPLITK, 2);   // 16 x 8 x 2
    const dim3 gg1(DD / GBN, (BB / GBM) * SPLITK, 1);

    // stage 1: partials of fake_region@W_fr^T (z=0) and h_out@W_ho^T (z=1) -> part1
    gemm_tf32_kernel<<<gg2, 256>>>(fake_region, W_fr, h_out, W_ho,
                                   nullptr, nullptr, 0, 0);
    // stage 2: X = act(sum part1 + bias) reconstructed in loader -> part2
    gemm_tf32_kernel<<<gg2, 256>>>(nullptr, W_fre, nullptr, W_hoe,
                                   b_fr, b_ho, 1, 1);
    // attention scores (ho_e / fr_e reconstructed from part2)
    score_kernel<<<dim3(BB, 13), 512>>>(conv_embed, W_a, b_a, b_fre, b_hoe);
    softmax_kernel<<<BB, 256>>>();
    // visAtt + ho (fr/ho reconstructed from part1), split-L partials
    wsum_part_kernel<<<dim3(2, BB, WSPL), 128>>>(conv_feat, b_fr, b_ho);
    // stage 3: X = wpart0+wpart1 in loader -> part1[0]
    gemm_tf32_kernel<<<gg1, 256>>>(nullptr, W_h, nullptr, W_h,
                                   nullptr, nullptr, 2, 0);
    // final: out = tanh(sum part1[0] + b_h)
    epi_kernel<<<BB * DD / 1024, 256>>>(out, b_h);
}

// round 12
// speedup vs baseline: 1.2813x; 1.1808x over previous
#include <cuda_runtime.h>
#include <math.h>

#define BB 128
#define LL 196
#define DD 1024
#define LP1 197

#define GBM 64
#define GBN 64
#define GBK 32
#define SPLITK 4
#define XS 36            // smem row stride: (36*g+t) mod 32 = 4g+t -> conflict-free
#define WSPL 4           // wsum L-split
#define WCH (LL / WSPL)  // 49

// ---------------- scratch (__device__ globals; no allocations allowed) -------
__device__ float g_fr[BB * DD];
__device__ float g_ho[BB * DD];
__device__ float g_fr_e[BB * DD];
__device__ float g_ho_e[BB * DD];
__device__ float g_scores[BB * LP1];
__device__ float g_PI[BB * LP1];
__device__ float g_part[2][SPLITK][BB * DD];   // GEMM split-K partials
__device__ float g_wpart[WSPL][BB * DD];       // wsum split-L partials

__device__ __forceinline__ float fast_tanh(float x) {
    float y;
    asm("tanh.approx.f32 %0, %1;" : "=f"(y) : "f"(x));
    return y;
}

__device__ __forceinline__ float tf32hi(float x) {
    unsigned u;
    asm("cvt.rna.tf32.f32 %0, %1;" : "=r"(u) : "f"(x));
    return __uint_as_float(u);
}

__device__ __forceinline__ void mma8(float d[4],
                                     float a0, float a1, float a2, float a3,
                                     float b0, float b1) {
    asm volatile(
        "mma.sync.aligned.m16n8k8.row.col.f32.tf32.tf32.f32 "
        "{%0,%1,%2,%3},{%4,%5,%6,%7},{%8,%9},{%0,%1,%2,%3};"
        : "+f"(d[0]), "+f"(d[1]), "+f"(d[2]), "+f"(d[3])
        : "r"(__float_as_uint(a0)), "r"(__float_as_uint(a1)),
          "r"(__float_as_uint(a2)), "r"(__float_as_uint(a3)),
          "r"(__float_as_uint(b0)), "r"(__float_as_uint(b1)));
}

// ---------------- tf32 GEMM, split-K, pipelined ------------------------------
// partial[m,n] = sum_{k chunk} X[m,k]*W[n,k].  A = tf32(X), B hi/lo in smem.
// grid: (16 nb, 2 mb x 4 sk, z), 256 threads.
// fuse_wsum: X elements = sum of the 4 g_wpart planes (cheap float4 adds).
__global__ void __launch_bounds__(256, 2) gemm_tf32_kernel(
    const float* __restrict__ X0, const float* __restrict__ W0,
    const float* __restrict__ X1, const float* __restrict__ W1,
    int fuse_wsum)
{
    __shared__ float Xh[GBM * XS];
    __shared__ float Wh[GBN * XS];
    __shared__ float Wl[GBN * XS];

    const int z  = blockIdx.z;
    const float* __restrict__ X = z ? X1 : X0;
    const float* __restrict__ W = z ? W1 : W0;
    const int nb = blockIdx.x;
    const int mb = blockIdx.y & 1;
    const int sk = blockIdx.y >> 1;
    const int kbase = sk * (DD / SPLITK);      // 256-wide K chunk, 8 iters

    const int tid  = threadIdx.x;
    const int lane = tid & 31;
    const int w    = tid >> 5;
    const int g    = lane >> 2;
    const int t    = lane & 3;
    const int wm   = (w & 3) * 16;             // 4 warps x 16 rows
    const int wn   = (w >> 2) * 32;            // 2 warps x 32 cols

    const int lr0 = tid >> 3;                  // loader rows 0..31
    const int lc4 = (tid & 7) * 4;
    const float* Xg = X + (size_t)(mb * GBM) * DD;
    const float* Wg = W + (size_t)(nb * GBN) * DD;
    const size_t wpoff = (size_t)(mb * GBM) * DD;

    float acc[4][4];
#pragma unroll
    for (int j = 0; j < 4; j++)
#pragma unroll
        for (int r = 0; r < 4; r++) acc[j][r] = 0.0f;

    // prologue: load iter 0
    {
        const int k0 = kbase;
#pragma unroll
        for (int j = 0; j < 2; ++j) {
            int row = lr0 + 32 * j;
            size_t off = (size_t)row * DD + k0 + lc4;
            float4 xv;
            if (fuse_wsum) {
                xv = *reinterpret_cast<const float4*>(&g_wpart[0][wpoff + off]);
#pragma unroll
                for (int p = 1; p < WSPL; ++p) {
                    float4 v = *reinterpret_cast<const float4*>(&g_wpart[p][wpoff + off]);
                    xv.x += v.x; xv.y += v.y; xv.z += v.z; xv.w += v.w;
                }
            } else {
                xv = *reinterpret_cast<const float4*>(Xg + off);
            }
            float4 wv = *reinterpret_cast<const float4*>(Wg + off);
            float4 h, wh, wl;
            h.x = tf32hi(xv.x); h.y = tf32hi(xv.y); h.z = tf32hi(xv.z); h.w = tf32hi(xv.w);
            wh.x = tf32hi(wv.x); wh.y = tf32hi(wv.y); wh.z = tf32hi(wv.z); wh.w = tf32hi(wv.w);
            wl.x = tf32hi(wv.x - wh.x); wl.y = tf32hi(wv.y - wh.y);
            wl.z = tf32hi(wv.z - wh.z); wl.w = tf32hi(wv.w - wh.w);
            *reinterpret_cast<float4*>(&Xh[row * XS + lc4]) = h;
            *reinterpret_cast<float4*>(&Wh[row * XS + lc4]) = wh;
            *reinterpret_cast<float4*>(&Wl[row * XS + lc4]) = wl;
        }
    }
    __syncthreads();

    for (int it = 0; it < 8; ++it) {
        float4 xr[2], wr[2];
        if (it < 7) {
            const int k0 = kbase + (it + 1) * GBK;
#pragma unroll
            for (int j = 0; j < 2; ++j) {
                int row = lr0 + 32 * j;
                size_t off = (size_t)row * DD + k0 + lc4;
                if (fuse_wsum) {
                    float4 u = *reinterpret_cast<const float4*>(&g_wpart[0][wpoff + off]);
#pragma unroll
                    for (int p = 1; p < WSPL; ++p) {
                        float4 v = *reinterpret_cast<const float4*>(&g_wpart[p][wpoff + off]);
                        u.x += v.x; u.y += v.y; u.z += v.z; u.w += v.w;
                    }
                    xr[j] = u;
                } else {
                    xr[j] = *reinterpret_cast<const float4*>(Xg + off);
                }
                wr[j] = *reinterpret_cast<const float4*>(Wg + off);
            }
        }

#pragma unroll
        for (int kk = 0; kk < 4; ++kk) {
            const int ko = 8 * kk;
            float a0 = Xh[(wm + g)     * XS + ko + t];
            float a1 = Xh[(wm + g + 8) * XS + ko + t];
            float a2 = Xh[(wm + g)     * XS + ko + t + 4];
            float a3 = Xh[(wm + g + 8) * XS + ko + t + 4];
#pragma unroll
            for (int j = 0; j < 4; ++j) {
                int n = (wn + 8 * j + g) * XS + ko + t;
                float bh0 = Wh[n];
                float bh1 = Wh[n + 4];
                float bl0 = Wl[n];
                float bl1 = Wl[n + 4];
                mma8(acc[j], a0, a1, a2, a3, bl0, bl1);
                mma8(acc[j], a0, a1, a2, a3, bh0, bh1);
            }
        }
        __syncthreads();

        if (it < 7) {
#pragma unroll
            for (int j = 0; j < 2; ++j) {
                int row = lr0 + 32 * j;
                float4 h, wh, wl;
                h.x = tf32hi(xr[j].x); h.y = tf32hi(xr[j].y);
                h.z = tf32hi(xr[j].z); h.w = tf32hi(xr[j].w);
                wh.x = tf32hi(wr[j].x); wh.y = tf32hi(wr[j].y);
                wh.z = tf32hi(wr[j].z); wh.w = tf32hi(wr[j].w);
                wl.x = tf32hi(wr[j].x - wh.x); wl.y = tf32hi(wr[j].y - wh.y);
                wl.z = tf32hi(wr[j].z - wh.z); wl.w = tf32hi(wr[j].w - wh.w);
                *reinterpret_cast<float4*>(&Xh[row * XS + lc4]) = h;
                *reinterpret_cast<float4*>(&Wh[row * XS + lc4]) = wh;
                *reinterpret_cast<float4*>(&Wl[row * XS + lc4]) = wl;
            }
            __syncthreads();
        }
    }

    // store partials: c0,c1 -> [m][2t,2t+1], c2,c3 -> [m+8][...]
    float* pout = &g_part[z][sk][0];
    const int mrow = mb * GBM + wm + g;
#pragma unroll
    for (int j = 0; j < 4; ++j) {
        int n = nb * GBN + wn + 8 * j + 2 * t;
        *reinterpret_cast<float2*>(&pout[(size_t)mrow * DD + n])       = make_float2(acc[j][0], acc[j][1]);
        *reinterpret_cast<float2*>(&pout[(size_t)(mrow + 8) * DD + n]) = make_float2(acc[j][2], acc[j][3]);
    }
}

// ---------------- epilogue: sum split-K partials + bias + act (float4) -------
__global__ void __launch_bounds__(256) epi_kernel(
    float* __restrict__ Y0, const float* __restrict__ b0, int act0,
    float* __restrict__ Y1, const float* __restrict__ b1, int act1)
{
    const int z = blockIdx.y;
    float* Y = z ? Y1 : Y0;
    const float* bias = z ? b1 : b0;
    const int act = z ? act1 : act0;
    const int i4 = (blockIdx.x * 256 + threadIdx.x) * 4;

    float4 s = *reinterpret_cast<const float4*>(&g_part[z][0][i4]);
#pragma unroll
    for (int p = 1; p < SPLITK; ++p) {
        float4 v = *reinterpret_cast<const float4*>(&g_part[z][p][i4]);
        s.x += v.x; s.y += v.y; s.z += v.z; s.w += v.w;
    }
    float4 bv = *reinterpret_cast<const float4*>(&bias[i4 & (DD - 1)]);
    s.x += bv.x; s.y += bv.y; s.z += bv.z; s.w += bv.w;
    if (act == 1) {
        s.x = fmaxf(s.x, 0.0f); s.y = fmaxf(s.y, 0.0f);
        s.z = fmaxf(s.z, 0.0f); s.w = fmaxf(s.w, 0.0f);
    } else if (act == 2) {
        s.x = tanhf(s.x); s.y = tanhf(s.y); s.z = tanhf(s.z); s.w = tanhf(s.w);
    }
    *reinterpret_cast<float4*>(&Y[i4]) = s;
}

// ---------------- scores: one warp per l, grid (B, 13), 512 threads ----------
__global__ void __launch_bounds__(512) score_kernel(const float* __restrict__ cfe,
                                                    const float* __restrict__ W_a,
                                                    const float* __restrict__ b_a)
{
    __shared__ __align__(16) float s_hoe[DD];
    __shared__ __align__(16) float s_wa[DD];

    const int b   = blockIdx.x;
    const int tid = threadIdx.x;
    for (int i = tid; i < DD; i += 512) {
        s_hoe[i] = g_ho_e[b * DD + i];
        s_wa[i]  = W_a[i];
    }
    __syncthreads();

    const int warp = tid >> 5;
    const int lane = tid & 31;
    const int l = blockIdx.y * 16 + warp;
    if (l >= LP1) return;

    const float* ebase = (l == 0) ? (g_fr_e + (size_t)b * DD)
                                  : (cfe + ((size_t)b * LL + (l - 1)) * (size_t)DD);
    float acc = 0.0f;
#pragma unroll
    for (int i = 0; i < 8; ++i) {
        int d = i * 128 + lane * 4;
        float4 e = *reinterpret_cast<const float4*>(ebase + d);
        float4 h = *reinterpret_cast<const float4*>(&s_hoe[d]);
        float4 a = *reinterpret_cast<const float4*>(&s_wa[d]);
        acc = fmaf(fast_tanh(e.x + h.x), a.x, acc);
        acc = fmaf(fast_tanh(e.y + h.y), a.y, acc);
        acc = fmaf(fast_tanh(e.z + h.z), a.z, acc);
        acc = fmaf(fast_tanh(e.w + h.w), a.w, acc);
    }
#pragma unroll
    for (int off = 16; off > 0; off >>= 1)
        acc += __shfl_down_sync(0xffffffffu, acc, off);
    if (lane == 0) g_scores[b * LP1 + l] = acc + b_a[0];
}

// ---------------- softmax over 197 scores, one CTA per b ---------------------
__global__ void softmax_kernel()
{
    __shared__ float s_red[8];
    const int b   = blockIdx.x;
    const int tid = threadIdx.x;
    const int warp = tid >> 5, lane = tid & 31;

    float v = (tid < LP1) ? g_scores[b * LP1 + tid] : -1e30f;
    float m = v;
#pragma unroll
    for (int off = 16; off > 0; off >>= 1)
        m = fmaxf(m, __shfl_xor_sync(0xffffffffu, m, off));
    if (lane == 0) s_red[warp] = m;
    __syncthreads();
    if (tid == 0) {
        float mm = s_red[0];
#pragma unroll
        for (int i = 1; i < 8; i++) mm = fmaxf(mm, s_red[i]);
        s_red[0] = mm;
    }
    __syncthreads();
    const float mx = s_red[0];
    float pv = (tid < LP1) ? expf(v - mx) : 0.0f;
    float ssum = pv;
#pragma unroll
    for (int off = 16; off > 0; off >>= 1)
        ssum += __shfl_xor_sync(0xffffffffu, ssum, off);
    __syncthreads();
    if (lane == 0) s_red[warp] = ssum;
    __syncthreads();
    if (tid == 0) {
        float tsum = 0.0f;
#pragma unroll
        for (int i = 0; i < 8; i++) tsum += s_red[i];
        s_red[0] = tsum;
    }
    __syncthreads();
    const float inv = 1.0f / s_red[0];
    if (tid < LP1) g_PI[b * LP1 + tid] = pv * inv;
}

// ---------------- weighted sum, split-L partials -----------------------------
__global__ void __launch_bounds__(128) wsum_part_kernel(const float* __restrict__ conv_feat)
{
    __shared__ float s_pi[WCH];
    const int b = blockIdx.y;
    const int s = blockIdx.z;
    const int d = blockIdx.x * 512 + threadIdx.x * 4;
    const int l0 = s * WCH;

    for (int i = threadIdx.x; i < WCH; i += 128)
        s_pi[i] = g_PI[b * LP1 + 1 + l0 + i];
    __syncthreads();

    float4 acc;
    if (s == 0) {
        const float p0 = g_PI[b * LP1];
        float4 fr4 = *reinterpret_cast<const float4*>(&g_fr[b * DD + d]);
        float4 ho4 = *reinterpret_cast<const float4*>(&g_ho[b * DD + d]);
        acc.x = fmaf(p0, fr4.x, ho4.x);
        acc.y = fmaf(p0, fr4.y, ho4.y);
        acc.z = fmaf(p0, fr4.z, ho4.z);
        acc.w = fmaf(p0, fr4.w, ho4.w);
    } else {
        acc = make_float4(0.0f, 0.0f, 0.0f, 0.0f);
    }

    const float* cf = conv_feat + ((size_t)b * LL + l0) * DD + d;
#pragma unroll 7
    for (int l = 0; l < WCH; ++l) {
        float4 v = *reinterpret_cast<const float4*>(cf + (size_t)l * DD);
        float p = s_pi[l];
        acc.x = fmaf(p, v.x, acc.x);
        acc.y = fmaf(p, v.y, acc.y);
        acc.z = fmaf(p, v.z, acc.z);
        acc.w = fmaf(p, v.w, acc.w);
    }
    *reinterpret_cast<float4*>(&g_wpart[s][b * DD + d]) = acc;
}

// ---------------- launch -----------------------------------------------------
extern "C" void kernel_launch(void* const* d_in, const int* in_sizes, int n_in,
                              void* d_out, int out_size)
{
    const float* h_out       = (const float*)d_in[0];
    const float* fake_region = (const float*)d_in[1];
    const float* conv_feat   = (const float*)d_in[2];
    const float* conv_embed  = (const float*)d_in[3];
    const float* W_fr  = (const float*)d_in[4];
    const float* b_fr  = (const float*)d_in[5];
    const float* W_fre = (const float*)d_in[6];
    const float* b_fre = (const float*)d_in[7];
    const float* W_ho  = (const float*)d_in[8];
    const float* b_ho  = (const float*)d_in[9];
    const float* W_hoe = (const float*)d_in[10];
    const float* b_hoe = (const float*)d_in[11];
    const float* W_a   = (const float*)d_in[12];
    const float* b_a   = (const float*)d_in[13];
    const float* W_h   = (const float*)d_in[14];
    const float* b_h   = (const float*)d_in[15];
    float* out = (float*)d_out;

    float *p_fr, *p_ho, *p_fr_e, *p_ho_e;
    cudaGetSymbolAddress((void**)&p_fr,   g_fr);
    cudaGetSymbolAddress((void**)&p_ho,   g_ho);
    cudaGetSymbolAddress((void**)&p_fr_e, g_fr_e);
    cudaGetSymbolAddress((void**)&p_ho_e, g_ho_e);

    const dim3 gg2(DD / GBN, (BB / GBM) * SPLITK, 2);   // 16 x 8 x 2
    const dim3 gg1(DD / GBN, (BB / GBM) * SPLITK, 1);
    const dim3 ge2(BB * DD / 1024, 2);                  // 128 x 2
    const dim3 ge1(BB * DD / 1024, 1);

    // stage 1: fr = relu(fake_region@W_fr^T+b), ho = tanh(h_out@W_ho^T+b)
    gemm_tf32_kernel<<<gg2, 256>>>(fake_region, W_fr, h_out, W_ho, 0);
    epi_kernel<<<ge2, 256>>>(p_fr, b_fr, 1, p_ho, b_ho, 2);
    // stage 2: fr_e, ho_e (no activation)
    gemm_tf32_kernel<<<gg2, 256>>>(p_fr, W_fre, p_ho, W_hoe, 0);
    epi_kernel<<<ge2, 256>>>(p_fr_e, b_fre, 0, p_ho_e, b_hoe, 0);
    // attention scores + softmax
    score_kernel<<<dim3(BB, 13), 512>>>(conv_embed, W_a, b_a);
    softmax_kernel<<<BB, 256>>>();
    // visAtt + ho, split-L partials (4 planes)
    wsum_part_kernel<<<dim3(2, BB, WSPL), 128>>>(conv_feat);
    // stage 3: h partials, X = sum of 4 wparts in loader
    gemm_tf32_kernel<<<gg1, 256>>>(nullptr, W_h, nullptr, W_h, 1);
    epi_kernel<<<ge1, 256>>>(out, b_h, 2, out, b_h, 2);
}